// round 3
// baseline (speedup 1.0000x reference)
#include <cuda_runtime.h>
#include <cstdint>

#define N_NODES 50000
#define N_EDGES 800000
#define NUM_GRAPHS 256
#define IN_DIM 128
#define H_DIM 64
#define HID 256
#define EPS 1e-5f

#define SCAN_B 1024
#define SCAN_NB ((N_NODES + SCAN_B - 1) / SCAN_B)   // 49

// ---------------- scratch (static device memory; no allocation) ----------------
__device__ int   g_is64;
__device__ int   g_src[N_EDGES];
__device__ int   g_dst[N_EDGES];
__device__ int   g_batch[N_NODES];
__device__ int   g_deg[N_NODES];
__device__ int   g_off[N_NODES];
__device__ int   g_cur[N_NODES];
__device__ int   g_csr[N_EDGES];
__device__ int   g_bsum[SCAN_NB];
__device__ int   g_boff[SCAN_NB];
__device__ float g_yl[N_NODES * H_DIM];
__device__ float g_yr[N_NODES * H_DIM];
__device__ float g_hA[N_NODES * H_DIM];
__device__ float g_hB[N_NODES * H_DIM];
__device__ float g_pool[NUM_GRAPHS * H_DIM];
__device__ float g_pcnt[NUM_GRAPHS];
__device__ float g_m1[NUM_GRAPHS * HID];
__device__ float g_m2[NUM_GRAPHS * (HID / 2)];
__device__ float g_m3[NUM_GRAPHS * (HID / 4)];

// Buffer selector so kernels address __device__ globals without any host-side
// cudaGetSymbolAddress (kernel_launch stays launches-only).
__device__ __forceinline__ float* buf_by_id(int id) {
    switch (id) {
        case 0: return g_yl;
        case 1: return g_yr;
        case 2: return g_hA;
        case 3: return g_hB;
        default: return g_pool;
    }
}

// ---------------- dtype probe: is edge_index int64 or int32? ----------------
__global__ void probe_kernel(const long long* __restrict__ e) {
    __shared__ int bad[256];
    int t = threadIdx.x;
    int b = 0;
    // first 1024 int64 slots = 8KB, in-bounds under both dtypes
    for (int i = t; i < 1024; i += 256) {
        long long v = e[i];
        if (v < 0 || v >= (long long)N_NODES) b = 1;
    }
    bad[t] = b;
    __syncthreads();
    for (int s = 128; s > 0; s >>= 1) {
        if (t < s) bad[t] |= bad[t + s];
        __syncthreads();
    }
    if (t == 0) g_is64 = bad[0] ? 0 : 1;
}

// ---------------- zero scratch (must run before convert_edges: deg histogram) ----
__global__ void zero_kernel() {
    int i = blockIdx.x * blockDim.x + threadIdx.x;
    if (i < N_NODES) g_deg[i] = 0;
    if (i < NUM_GRAPHS * H_DIM) g_pool[i] = 0.0f;
    if (i < NUM_GRAPHS) g_pcnt[i] = 0.0f;
}

// convert + degree histogram fused
__global__ void convert_edges(const void* __restrict__ e) {
    int i = blockIdx.x * blockDim.x + threadIdx.x;
    if (i >= N_EDGES) return;
    int s, d;
    if (g_is64) {
        const long long* p = (const long long*)e;
        s = (int)p[i];
        d = (int)p[N_EDGES + i];
    } else {
        const int* p = (const int*)e;
        s = p[i];
        d = p[N_EDGES + i];
    }
    g_src[i] = s;
    g_dst[i] = d;
    atomicAdd(&g_deg[d], 1);
}

__global__ void convert_batch(const void* __restrict__ bptr) {
    int i = blockIdx.x * blockDim.x + threadIdx.x;
    if (i >= N_NODES) return;
    if (g_is64) g_batch[i] = (int)((const long long*)bptr)[i];
    else        g_batch[i] = ((const int*)bptr)[i];
}

// ---------------- CSR build ----------------
__global__ void blocksum_kernel() {
    __shared__ int s[SCAN_B];
    int t = threadIdx.x;
    int i = blockIdx.x * SCAN_B + t;
    s[t] = (i < N_NODES) ? g_deg[i] : 0;
    __syncthreads();
    for (int st = SCAN_B / 2; st > 0; st >>= 1) {
        if (t < st) s[t] += s[t + st];
        __syncthreads();
    }
    if (t == 0) g_bsum[blockIdx.x] = s[0];
}

__global__ void scan_bsum_kernel() {
    int run = 0;
    for (int i = 0; i < SCAN_NB; i++) { g_boff[i] = run; run += g_bsum[i]; }
}

__global__ void block_scan_kernel() {
    __shared__ int s[SCAN_B];
    int t = threadIdx.x;
    int i = blockIdx.x * SCAN_B + t;
    int v = (i < N_NODES) ? g_deg[i] : 0;
    s[t] = v;
    __syncthreads();
    for (int off = 1; off < SCAN_B; off <<= 1) {
        int x = (t >= off) ? s[t - off] : 0;
        __syncthreads();
        s[t] += x;
        __syncthreads();
    }
    if (i < N_NODES) {
        int o = g_boff[blockIdx.x] + s[t] - v;  // exclusive
        g_off[i] = o;
        g_cur[i] = o;
    }
}

__global__ void fill_kernel() {
    int i = blockIdx.x * blockDim.x + threadIdx.x;
    if (i < N_EDGES) {
        int p = atomicAdd(&g_cur[g_dst[i]], 1);
        g_csr[p] = g_src[i];
    }
}

// ---------------- dual GEMM: yl = in@Wl, yr = in@Wr + b   (Nout = 64) ----------------
// BM=128, BN=64, BK=16, 256 threads, thread tile 8x4 (x2 outputs)
// in_id < 0 -> use external pointer `xin` (layer-1 input), else buf_by_id.
__global__ __launch_bounds__(256)
void gemm_dual(const float* __restrict__ xin, int in_id,
               const float* __restrict__ Wl,
               const float* __restrict__ bias, const float* __restrict__ Wr,
               int K) {
    const float* in = (in_id < 0) ? xin : buf_by_id(in_id);
    const int M = N_NODES;

    __shared__ float sA[16][128];
    __shared__ float sBl[16][64];
    __shared__ float sBr[16][64];

    int tid = threadIdx.x;
    int tx = tid & 15;
    int ty = tid >> 4;
    int tx4 = tx * 4;
    int ty8 = ty * 8;
    int rowBase = blockIdx.x * 128;

    float accL[8][4];
    float accR[8][4];
#pragma unroll
    for (int i = 0; i < 8; i++)
#pragma unroll
        for (int c = 0; c < 4; c++) { accL[i][c] = 0.0f; accR[i][c] = 0.0f; }

    for (int k0 = 0; k0 < K; k0 += 16) {
#pragma unroll
        for (int l = 0; l < 2; l++) {
            int li = tid + l * 256;
            int nl = li >> 2;
            int kq = li & 3;
            int node = rowBase + nl;
            float4 v = make_float4(0.f, 0.f, 0.f, 0.f);
            if (node < M) v = *(const float4*)(in + (size_t)node * K + k0 + kq * 4);
            sA[kq * 4 + 0][nl] = v.x;
            sA[kq * 4 + 1][nl] = v.y;
            sA[kq * 4 + 2][nl] = v.z;
            sA[kq * 4 + 3][nl] = v.w;
        }
        {
            int kk = tid >> 4;
            int jq = tid & 15;
            float4 vl = *(const float4*)(Wl + (size_t)(k0 + kk) * 64 + jq * 4);
            float4 vr = *(const float4*)(Wr + (size_t)(k0 + kk) * 64 + jq * 4);
            *(float4*)&sBl[kk][jq * 4] = vl;
            *(float4*)&sBr[kk][jq * 4] = vr;
        }
        __syncthreads();

#pragma unroll
        for (int kk = 0; kk < 16; kk++) {
            float4 a0 = *(const float4*)&sA[kk][ty8];
            float4 a1 = *(const float4*)&sA[kk][ty8 + 4];
            float4 b0 = *(const float4*)&sBl[kk][tx4];
            float4 c0 = *(const float4*)&sBr[kk][tx4];
            float a[8] = {a0.x, a0.y, a0.z, a0.w, a1.x, a1.y, a1.z, a1.w};
#pragma unroll
            for (int i = 0; i < 8; i++) {
                accL[i][0] += a[i] * b0.x;
                accL[i][1] += a[i] * b0.y;
                accL[i][2] += a[i] * b0.z;
                accL[i][3] += a[i] * b0.w;
                accR[i][0] += a[i] * c0.x;
                accR[i][1] += a[i] * c0.y;
                accR[i][2] += a[i] * c0.z;
                accR[i][3] += a[i] * c0.w;
            }
        }
        __syncthreads();
    }

    float4 bb = *(const float4*)(bias + tx4);
#pragma unroll
    for (int i = 0; i < 8; i++) {
        int node = rowBase + ty8 + i;
        if (node < M) {
            float4 ol = make_float4(accL[i][0], accL[i][1], accL[i][2], accL[i][3]);
            float4 orr = make_float4(accR[i][0] + bb.x, accR[i][1] + bb.y,
                                     accR[i][2] + bb.z, accR[i][3] + bb.w);
            *(float4*)(g_yl + (size_t)node * 64 + tx4) = ol;
            *(float4*)(g_yr + (size_t)node * 64 + tx4) = orr;
        }
    }
}

// ---------------- aggregation: out[n] = mean_{e in CSR(n)} yl[src_e] + yr[n] ----------------
__global__ void aggregate_kernel(int out_id) {
    float* out = buf_by_id(out_id);
    int warp = (blockIdx.x * blockDim.x + threadIdx.x) >> 5;
    int lane = threadIdx.x & 31;
    if (warp >= N_NODES) return;
    int start = g_off[warp];
    int d = g_deg[warp];
    float ax = 0.0f, ay = 0.0f;
    for (int e = 0; e < d; e++) {
        int s = g_csr[start + e];
        float2 v = *(const float2*)(g_yl + (size_t)s * 64 + lane * 2);
        ax += v.x;
        ay += v.y;
    }
    float inv = (d > 0) ? (1.0f / (float)d) : 0.0f;
    float2 r = *(const float2*)(g_yr + (size_t)warp * 64 + lane * 2);
    float2 o;
    o.x = ax * inv + r.x;
    o.y = ay * inv + r.y;
    *(float2*)(out + (size_t)warp * 64 + lane * 2) = o;
}

// ---------------- global mean pool (batch sorted) ----------------
__global__ void pool_kernel(int in_id) {
    const float* h = buf_by_id(in_id);
    int f = threadIdx.x & 63;
    int sub = threadIdx.x >> 6;
    int base = blockIdx.x * 128 + sub * 32;
    if (base >= N_NODES) return;
    int end = base + 32;
    if (end > N_NODES) end = N_NODES;
    float run = 0.0f, cnt = 0.0f;
    int cur = -1;
    for (int n = base; n < end; n++) {
        int b = g_batch[n];
        if (b != cur) {
            if (cur >= 0) {
                atomicAdd(&g_pool[cur * 64 + f], run);
                if (f == 0) atomicAdd(&g_pcnt[cur], cnt);
            }
            run = 0.0f; cnt = 0.0f; cur = b;
        }
        run += h[(size_t)n * 64 + f];
        cnt += 1.0f;
    }
    if (cur >= 0) {
        atomicAdd(&g_pool[cur * 64 + f], run);
        if (f == 0) atomicAdd(&g_pcnt[cur], cnt);
    }
}

// ---------------- MLP head ----------------
// stage 0: pool->m1 (divides pool rows by counts on the fly)
// stage 1: m1->m2   stage 2: m2->m3   stage 3: m3->ext_out
__global__ void mlp_gemm(int stage, const float* __restrict__ W,
                         const float* __restrict__ b, float* __restrict__ ext_out,
                         int K, int Nout) {
    const float* in;
    float* out;
    switch (stage) {
        case 0: in = g_pool; out = g_m1; break;
        case 1: in = g_m1;   out = g_m2; break;
        case 2: in = g_m2;   out = g_m3; break;
        default: in = g_m3;  out = ext_out; break;
    }
    int idx = blockIdx.x * blockDim.x + threadIdx.x;
    if (idx >= NUM_GRAPHS * Nout) return;
    int r = idx / Nout;
    int j = idx - r * Nout;
    float scale = 1.0f;
    if (stage == 0) scale = 1.0f / fmaxf(g_pcnt[r], 1.0f);
    float acc = b[j];
    const float* ir = in + (size_t)r * K;
    for (int k = 0; k < K; k++) acc += ir[k] * W[(size_t)k * Nout + j];
    // scale applies to input contribution only, not the bias:
    // out = (scale * in_row) @ W + b  ==  scale*(in_row@W) + b
    if (stage == 0) acc = (acc - b[j]) * scale + b[j];
    out[idx] = acc;
}

// one block per column; blockDim = NUM_GRAPHS = 256
// which: 0 -> g_m1, 1 -> g_m2, 2 -> g_m3
__global__ void bn_tanh_kernel(int which, const float* __restrict__ g,
                               const float* __restrict__ be, int ncols) {
    float* y = (which == 0) ? g_m1 : (which == 1) ? g_m2 : g_m3;
    __shared__ float sd[256];
    __shared__ float sm[2];
    int j = blockIdx.x;
    int t = threadIdx.x;
    float v = y[(size_t)t * ncols + j];
    sd[t] = v;
    __syncthreads();
    for (int s = 128; s > 0; s >>= 1) {
        if (t < s) sd[t] += sd[t + s];
        __syncthreads();
    }
    if (t == 0) sm[0] = sd[0] * (1.0f / NUM_GRAPHS);
    __syncthreads();
    float mean = sm[0];
    float d = v - mean;
    sd[t] = d * d;
    __syncthreads();
    for (int s = 128; s > 0; s >>= 1) {
        if (t < s) sd[t] += sd[t + s];
        __syncthreads();
    }
    if (t == 0) sm[1] = sd[0] * (1.0f / NUM_GRAPHS);
    __syncthreads();
    float var = sm[1];
    float o = d * rsqrtf(var + EPS) * g[j] + be[j];
    y[(size_t)t * ncols + j] = tanhf(o);
}

// ---------------- launch ----------------
extern "C" void kernel_launch(void* const* d_in, const int* in_sizes, int n_in,
                              void* d_out, int out_size) {
    const float* x     = (const float*)d_in[0];
    const void*  eidx  = d_in[1];
    const void*  batch = d_in[2];
    const float* W1l = (const float*)d_in[3];
    const float* b1l = (const float*)d_in[4];
    const float* W1r = (const float*)d_in[5];
    const float* W2l = (const float*)d_in[6];
    const float* b2l = (const float*)d_in[7];
    const float* W2r = (const float*)d_in[8];
    const float* W3l = (const float*)d_in[9];
    const float* b3l = (const float*)d_in[10];
    const float* W3r = (const float*)d_in[11];
    const float* lin1_w = (const float*)d_in[12];
    const float* lin1_b = (const float*)d_in[13];
    const float* g1  = (const float*)d_in[14];
    const float* be1 = (const float*)d_in[15];
    const float* lin2_w = (const float*)d_in[16];
    const float* lin2_b = (const float*)d_in[17];
    const float* g2  = (const float*)d_in[18];
    const float* be2 = (const float*)d_in[19];
    const float* lin3_w = (const float*)d_in[20];
    const float* lin3_b = (const float*)d_in[21];
    const float* g3  = (const float*)d_in[22];
    const float* be3 = (const float*)d_in[23];
    const float* lin4_w = (const float*)d_in[24];
    const float* lin4_b = (const float*)d_in[25];
    float* out = (float*)d_out;

    const int EB = (N_EDGES + 255) / 256;      // 3125
    const int NBn = (N_NODES + 255) / 256;     // 196
    const int GB = (N_NODES + 127) / 128;      // 391
    const int AB = (N_NODES * 32 + 255) / 256; // 6250

    // dtype normalization + per-call zeroing (zero BEFORE convert: fused histogram)
    probe_kernel<<<1, 256>>>((const long long*)eidx);
    zero_kernel<<<NBn, 256>>>();
    convert_edges<<<EB, 256>>>(eidx);
    convert_batch<<<NBn, 256>>>(batch);

    // CSR build
    blocksum_kernel<<<SCAN_NB, SCAN_B>>>();
    scan_bsum_kernel<<<1, 1>>>();
    block_scan_kernel<<<SCAN_NB, SCAN_B>>>();
    fill_kernel<<<EB, 256>>>();

    // Layer 1: linear-first, then aggregate 64-dim   (hA = buf 2, hB = buf 3)
    gemm_dual<<<GB, 256>>>(x, -1, W1l, b1l, W1r, IN_DIM);
    aggregate_kernel<<<AB, 256>>>(2);
    // Layer 2
    gemm_dual<<<GB, 256>>>(nullptr, 2, W2l, b2l, W2r, H_DIM);
    aggregate_kernel<<<AB, 256>>>(3);
    // Layer 3
    gemm_dual<<<GB, 256>>>(nullptr, 3, W3l, b3l, W3r, H_DIM);
    aggregate_kernel<<<AB, 256>>>(2);

    // global mean pool (division folded into mlp stage 0)
    pool_kernel<<<GB, 256>>>(2);

    // MLP head
    mlp_gemm<<<(NUM_GRAPHS * HID + 255) / 256, 256>>>(0, lin1_w, lin1_b, nullptr,
                                                      H_DIM, HID);
    bn_tanh_kernel<<<HID, 256>>>(0, g1, be1, HID);
    mlp_gemm<<<(NUM_GRAPHS * (HID / 2) + 255) / 256, 256>>>(1, lin2_w, lin2_b, nullptr,
                                                            HID, HID / 2);
    bn_tanh_kernel<<<HID / 2, 256>>>(1, g2, be2, HID / 2);
    mlp_gemm<<<(NUM_GRAPHS * (HID / 4) + 255) / 256, 256>>>(2, lin3_w, lin3_b, nullptr,
                                                            HID / 2, HID / 4);
    bn_tanh_kernel<<<HID / 4, 256>>>(2, g3, be3, HID / 4);
    mlp_gemm<<<(NUM_GRAPHS * 10 + 255) / 256, 256>>>(3, lin4_w, lin4_b, out,
                                                     HID / 4, 10);
}